// round 12
// baseline (speedup 1.0000x reference)
#include <cuda_runtime.h>

#define BB 4
#define SS 4096
#define DD 512
#define HH 64
#define NROW (BB * SS)   // 16384

__device__ float g_Q[NROW * HH];
__device__ float g_K[NROW * HH];
__device__ float g_Vt[NROW * HH];          // V transposed: [b][d][s], s contiguous
__device__ float g_O[NROW * HH];
__device__ float g_Opart[4 * NROW * HH];   // unnormalized partial O (4 slots)
__device__ float g_ML[4 * NROW * 2];       // (m, l) per slot per row
__device__ float g_Wt[3 * HH * DD];        // Wq/Wk/Wv transposed: [n][k], k contig
__device__ float g_Wot[DD * HH];           // Wo transposed: [n][k], k contig
__device__ unsigned g_ctr;

__device__ __forceinline__ unsigned f2tf32(float f) {
    unsigned u;
    asm("cvt.rna.tf32.f32 %0, %1;" : "=r"(u) : "f"(f));
    return u;
}
__device__ __forceinline__ float rne(float f) { return __uint_as_float(f2tf32(f)); }

__device__ __forceinline__ void mma_tf32(float (&d)[4], const unsigned (&a)[4],
                                         const unsigned (&b)[2]) {
    asm volatile(
        "mma.sync.aligned.m16n8k8.row.col.f32.tf32.tf32.f32 "
        "{%0,%1,%2,%3}, {%4,%5,%6,%7}, {%8,%9}, {%0,%1,%2,%3};"
        : "+f"(d[0]), "+f"(d[1]), "+f"(d[2]), "+f"(d[3])
        : "r"(a[0]), "r"(a[1]), "r"(a[2]), "r"(a[3]), "r"(b[0]), "r"(b[1]));
}
#define FU __float_as_uint

// ============================================================================
// Kernel 0: one-shot weight transpose + tf32 rounding (removes all in-loop
// rne on weights and enables vectorized B fragments everywhere).
// ============================================================================
__global__ __launch_bounds__(256) void prep_weights(
    const float* __restrict__ Wq, const float* __restrict__ Wk,
    const float* __restrict__ Wv, const float* __restrict__ Wo)
{
    int which = blockIdx.y;
    if (which == 0 && blockIdx.x == 0 && threadIdx.x == 0) g_ctr = 0u;
    int i = blockIdx.x * 256 + threadIdx.x;      // 0 .. 32767
    if (which < 3) {
        const float* W = (which == 0) ? Wq : (which == 1) ? Wk : Wv;
        int k = i >> 6, n = i & 63;              // W[k][n], [512][64]
        g_Wt[which * HH * DD + n * DD + k] = rne(W[i]);
    } else {
        int k = i >> 9, n = i & 511;             // Wo[k][n], [64][512]
        g_Wot[n * HH + k] = rne(Wo[i]);
    }
}

// ============================================================================
// Kernel 1: QKV projections, tf32 mma, register-prefetch over K chunks.
// 256 thr / 8 warps, M-tile 128.  Xs [128][80]; Ws [64][80] n-major (k contig)
// -> ALL fragments are conflict-free LDS.128.  V written transposed (rne'd).
// ============================================================================
__global__ __launch_bounds__(256) void qkv_tf32_kernel(
    const float* __restrict__ x,
    const float* __restrict__ bq, const float* __restrict__ bk,
    const float* __restrict__ bv)
{
    extern __shared__ float sm[];
    float* Xs = sm;              // 128 x 80
    float* Ws = sm + 128 * 80;   // 64 x 80

    int which = blockIdx.y;
    const float* Wt = g_Wt + which * HH * DD;
    const float* bias = (which == 0) ? bq : (which == 1) ? bk : bv;

    const int row0 = blockIdx.x * 128;
    const int t = threadIdx.x, w = t >> 5, lane = t & 31;
    const int qd = lane & 3, ln4 = lane >> 2;
    const int rowA = 16 * w + ln4;

    float acc[8][4];
#pragma unroll
    for (int nt = 0; nt < 8; nt++)
#pragma unroll
        for (int v = 0; v < 4; v++) acc[nt][v] = 0.f;

    float4 xr[8], wr[4];
#pragma unroll
    for (int l = 0; l < 8; l++) {
        int u = t + l * 256, r = u >> 4, c4 = u & 15;
        xr[l] = *(const float4*)(x + (size_t)(row0 + r) * DD + c4 * 4);
    }
#pragma unroll
    for (int l = 0; l < 4; l++) {
        int u = t + l * 256, r = u >> 4, c4 = u & 15;    // r = n-row
        wr[l] = *(const float4*)(Wt + (size_t)r * DD + c4 * 4);
    }

    for (int k0 = 0; k0 < DD; k0 += 64) {
        __syncthreads();
#pragma unroll
        for (int l = 0; l < 8; l++) {
            int u = t + l * 256, r = u >> 4, c4 = u & 15;
            float4 v = xr[l];
            v.x = rne(v.x); v.y = rne(v.y); v.z = rne(v.z); v.w = rne(v.w);
            *(float4*)&Xs[r * 80 + c4 * 4] = v;
        }
#pragma unroll
        for (int l = 0; l < 4; l++) {
            int u = t + l * 256, r = u >> 4, c4 = u & 15;
            *(float4*)&Ws[r * 80 + c4 * 4] = wr[l];      // pre-rounded
        }
        __syncthreads();

        if (k0 + 64 < DD) {   // prefetch next chunk under the MMAs
#pragma unroll
            for (int l = 0; l < 8; l++) {
                int u = t + l * 256, r = u >> 4, c4 = u & 15;
                xr[l] = *(const float4*)(x + (size_t)(row0 + r) * DD + (k0 + 64) + c4 * 4);
            }
#pragma unroll
            for (int l = 0; l < 4; l++) {
                int u = t + l * 256, r = u >> 4, c4 = u & 15;
                wr[l] = *(const float4*)(Wt + (size_t)r * DD + (k0 + 64) + c4 * 4);
            }
        }

#pragma unroll
        for (int jj = 0; jj < 4; jj++) {
            int ub = (qd + 4 * jj) * 4;
            float4 f0 = *(float4*)&Xs[rowA * 80 + ub];
            float4 f1 = *(float4*)&Xs[(rowA + 8) * 80 + ub];
            unsigned a0[4] = {FU(f0.x), FU(f1.x), FU(f0.y), FU(f1.y)};
            unsigned a1[4] = {FU(f0.z), FU(f1.z), FU(f0.w), FU(f1.w)};
#pragma unroll
            for (int nt = 0; nt < 8; nt++) {
                float4 fW = *(float4*)&Ws[(8 * nt + ln4) * 80 + ub];
                unsigned b0[2] = {FU(fW.x), FU(fW.y)};
                unsigned b1[2] = {FU(fW.z), FU(fW.w)};
                mma_tf32(acc[nt], a0, b0);
                mma_tf32(acc[nt], a1, b1);
            }
        }
    }

    if (which != 2) {
        float* out = (which == 0) ? g_Q : g_K;
#pragma unroll
        for (int nt = 0; nt < 8; nt++) {
            int c = 8 * nt + 2 * qd;
            int row = row0 + rowA;
            float b0 = bias[c], b1 = bias[c + 1];
            float2 v0 = {acc[nt][0] + b0, acc[nt][1] + b1};
            float2 v1 = {acc[nt][2] + b0, acc[nt][3] + b1};
            *(float2*)(out + (size_t)row * HH + c)       = v0;
            *(float2*)(out + (size_t)(row + 8) * HH + c) = v1;
        }
    } else {
        // V: write transposed [b][d][s] with tf32 rounding at source
        int row = row0 + rowA;
        int b = row >> 12, s = row & 4095;
        float* Vb = g_Vt + (size_t)b * HH * SS;
#pragma unroll
        for (int nt = 0; nt < 8; nt++) {
            int c = 8 * nt + 2 * qd;
            float b0 = bias[c], b1 = bias[c + 1];
            Vb[(size_t)c * SS + s]           = rne(acc[nt][0] + b0);
            Vb[(size_t)(c + 1) * SS + s]     = rne(acc[nt][1] + b1);
            Vb[(size_t)c * SS + s + 8]       = rne(acc[nt][2] + b0);
            Vb[(size_t)(c + 1) * SS + s + 8] = rne(acc[nt][3] + b1);
        }
    }
}

// ============================================================================
// Kernel 2: causal flash attention, tf32 mma, fine split-KV + K/V prefetch.
// V is pre-transposed -> GEMM2 B fragments are conflict-free LDS.128 (same
// permuted-k mapping as GEMM1).  P overlays the Ks buffer (barrier-guarded)
// -> smem 61440B -> 3 blocks/SM (launch_bounds (128,3)).
// ============================================================================
__global__ __launch_bounds__(128, 3) void flash_tf32_kernel()
{
    extern __shared__ float sm[];
    float* Qs  = sm;                  // 64 x 80
    float* Ks  = sm + 64 * 80;        // 64 x 80  (doubles as Ps)
    float* Vst = sm + 2 * 64 * 80;    // 64 x 80  (V^T tile: [d][s])
    float* Ps  = Ks;
    __shared__ unsigned s_tile;

    const int t = threadIdx.x, w = t >> 5, lane = t & 31;
    const int qd = lane & 3, ln4 = lane >> 2;
    const int rowA = 16 * w + ln4;
    const float scale = 0.015625f * 1.44269504089f;  // 1/sqrt(4096) * log2(e)

    while (true) {
        if (t == 0) s_tile = atomicAdd(&g_ctr, 1u);
        __syncthreads();
        unsigned i = s_tile;
        if (i >= 704u) break;

        int mt, b, part, jlo, jhi, split;
        if (i < 512u) {                       // mt 63..32, 4-way split
            mt = 63 - (int)(i >> 4);
            int sub = (int)(i & 15u);
            b = sub >> 2; part = sub & 3; split = 1;
            jlo = ((mt + 1) * part) >> 2;
            jhi = (((mt + 1) * (part + 1)) >> 2) - 1;
        } else if (i < 640u) {                // mt 31..16, 2-way split
            unsigned u = i - 512u;
            mt = 31 - (int)(u >> 3);
            int sub = (int)(u & 7u);
            b = sub >> 1; part = sub & 1; split = 1;
            jlo = ((mt + 1) * part) >> 1;
            jhi = (((mt + 1) * (part + 1)) >> 1) - 1;
        } else {                              // mt 15..0, unsplit
            unsigned u = i - 640u;
            mt = 15 - (int)(u >> 2);
            b = (int)(u & 3u);
            part = 0; split = 0; jlo = 0; jhi = mt;
        }
        const int q0 = mt * 64;

        const float* Qg = g_Q + ((size_t)b * SS + q0) * HH;
#pragma unroll
        for (int l = 0; l < 8; l++) {
            int u = t + l * 128, r = u >> 4, c4 = u & 15;
            *(float4*)&Qs[r * 80 + c4 * 4] = *(const float4*)(Qg + r * HH + c4 * 4);
        }

        // prologue prefetch of K / V^T tile jlo
        float4 kr[8], vr[8];
        {
            const float* Kg = g_K + ((size_t)b * SS + jlo * 64) * HH;
            const float* Vg = g_Vt + (size_t)b * HH * SS + jlo * 64;
#pragma unroll
            for (int l = 0; l < 8; l++) {
                int u = t + l * 128, r = u >> 4, c4 = u & 15;
                kr[l] = *(const float4*)(Kg + r * HH + c4 * 4);
                vr[l] = *(const float4*)(Vg + (size_t)r * SS + c4 * 4);
            }
        }

        float o_acc[8][4];
        float m_run[2] = {-1e30f, -1e30f};
        float l_run[2] = {0.f, 0.f};
#pragma unroll
        for (int nt = 0; nt < 8; nt++)
#pragma unroll
            for (int v = 0; v < 4; v++) o_acc[nt][v] = 0.f;

        for (int jt = jlo; jt <= jhi; jt++) {
            __syncthreads();
#pragma unroll
            for (int l = 0; l < 8; l++) {
                int u = t + l * 128, r = u >> 4, c4 = u & 15;
                *(float4*)&Ks[r * 80 + c4 * 4]  = kr[l];
                *(float4*)&Vst[r * 80 + c4 * 4] = vr[l];   // pre-rounded V^T
            }
            __syncthreads();

            if (jt < jhi) {   // prefetch next K/V^T under the compute
                const float* Kg = g_K + ((size_t)b * SS + (jt + 1) * 64) * HH;
                const float* Vg = g_Vt + (size_t)b * HH * SS + (jt + 1) * 64;
#pragma unroll
                for (int l = 0; l < 8; l++) {
                    int u = t + l * 128, r = u >> 4, c4 = u & 15;
                    kr[l] = *(const float4*)(Kg + r * HH + c4 * 4);
                    vr[l] = *(const float4*)(Vg + (size_t)r * SS + c4 * 4);
                }
            }

            // ---- GEMM1: S = Q K^T ----
            float s_acc[8][4];
#pragma unroll
            for (int nt = 0; nt < 8; nt++)
#pragma unroll
                for (int v = 0; v < 4; v++) s_acc[nt][v] = 0.f;

#pragma unroll
            for (int jj = 0; jj < 4; jj++) {
                int ub = (qd + 4 * jj) * 4;
                float4 fA = *(float4*)&Qs[rowA * 80 + ub];
                float4 fB = *(float4*)&Qs[(rowA + 8) * 80 + ub];
                unsigned a0[4] = {FU(fA.x), FU(fB.x), FU(fA.y), FU(fB.y)};
                unsigned a1[4] = {FU(fA.z), FU(fB.z), FU(fA.w), FU(fB.w)};
#pragma unroll
                for (int nt = 0; nt < 8; nt++) {
                    float4 fK = *(float4*)&Ks[(8 * nt + ln4) * 80 + ub];
                    unsigned b0[2] = {FU(fK.x), FU(fK.y)};
                    unsigned b1[2] = {FU(fK.z), FU(fK.w)};
                    mma_tf32(s_acc[nt], a0, b0);
                    mma_tf32(s_acc[nt], a1, b1);
                }
            }

            // ---- scale (log2-domain) + causal mask (diagonal tile only) ----
            if (jt == mt) {
#pragma unroll
                for (int nt = 0; nt < 8; nt++)
#pragma unroll
                    for (int v = 0; v < 4; v++) {
                        int row = rowA + ((v >= 2) ? 8 : 0);
                        int col = 8 * nt + 2 * qd + (v & 1);
                        s_acc[nt][v] = (col > row) ? -1e30f : s_acc[nt][v] * scale;
                    }
            } else {
#pragma unroll
                for (int nt = 0; nt < 8; nt++)
#pragma unroll
                    for (int v = 0; v < 4; v++) s_acc[nt][v] *= scale;
            }

            // ---- online softmax (base-2 domain) ----
#pragma unroll
            for (int rr = 0; rr < 2; rr++) {
                float mx = -1e30f;
#pragma unroll
                for (int nt = 0; nt < 8; nt++)
                    mx = fmaxf(mx, fmaxf(s_acc[nt][2 * rr], s_acc[nt][2 * rr + 1]));
                mx = fmaxf(mx, __shfl_xor_sync(0xffffffffu, mx, 1));
                mx = fmaxf(mx, __shfl_xor_sync(0xffffffffu, mx, 2));
                float mnew  = fmaxf(m_run[rr], mx);
                float alpha = exp2f(m_run[rr] - mnew);
                float rs = 0.f;
#pragma unroll
                for (int nt = 0; nt < 8; nt++) {
                    float p0 = exp2f(s_acc[nt][2 * rr]     - mnew);
                    float p1 = exp2f(s_acc[nt][2 * rr + 1] - mnew);
                    rs += p0 + p1;
                    s_acc[nt][2 * rr]     = p0;
                    s_acc[nt][2 * rr + 1] = p1;
                }
                rs += __shfl_xor_sync(0xffffffffu, rs, 1);
                rs += __shfl_xor_sync(0xffffffffu, rs, 2);
                l_run[rr] = l_run[rr] * alpha + rs;
                m_run[rr] = mnew;
#pragma unroll
                for (int nt = 0; nt < 8; nt++) {
                    o_acc[nt][2 * rr]     *= alpha;
                    o_acc[nt][2 * rr + 1] *= alpha;
                }
            }

            // ---- stash P into the Ks buffer (all GEMM1 reads done) ----
            __syncthreads();
#pragma unroll
            for (int nt = 0; nt < 8; nt++) {
                float2 p0 = {rne(s_acc[nt][0]), rne(s_acc[nt][1])};
                float2 p1 = {rne(s_acc[nt][2]), rne(s_acc[nt][3])};
                *(float2*)&Ps[rowA * 80 + 8 * nt + 2 * qd]       = p0;
                *(float2*)&Ps[(rowA + 8) * 80 + 8 * nt + 2 * qd] = p1;
            }
            __syncwarp();

            // ---- GEMM2: O += P V  (V^T k-contiguous -> all LDS.128) ----
#pragma unroll
            for (int jj = 0; jj < 4; jj++) {
                int ub = (qd + 4 * jj) * 4;
                float4 fA0 = *(float4*)&Ps[rowA * 80 + ub];
                float4 fA1 = *(float4*)&Ps[(rowA + 8) * 80 + ub];
                unsigned a0[4] = {FU(fA0.x), FU(fA1.x), FU(fA0.y), FU(fA1.y)};
                unsigned a1[4] = {FU(fA0.z), FU(fA1.z), FU(fA0.w), FU(fA1.w)};
#pragma unroll
                for (int nt = 0; nt < 8; nt++) {
                    float4 fV = *(float4*)&Vst[(8 * nt + ln4) * 80 + ub];
                    unsigned b0[2] = {FU(fV.x), FU(fV.y)};
                    unsigned b1[2] = {FU(fV.z), FU(fV.w)};
                    mma_tf32(o_acc[nt], a0, b0);
                    mma_tf32(o_acc[nt], a1, b1);
                }
            }
        }

        // ---- epilogue ----
        if (!split) {
            float inv0 = 1.f / l_run[0];
            float inv1 = 1.f / l_run[1];
            float* Og = g_O + ((size_t)b * SS + q0) * HH;
#pragma unroll
            for (int nt = 0; nt < 8; nt++) {
                float2 o0 = {o_acc[nt][0] * inv0, o_acc[nt][1] * inv0};
                float2 o1 = {o_acc[nt][2] * inv1, o_acc[nt][3] * inv1};
                *(float2*)&Og[rowA * HH + 8 * nt + 2 * qd]       = o0;
                *(float2*)&Og[(rowA + 8) * HH + 8 * nt + 2 * qd] = o1;
            }
        } else {
            size_t rbase = (size_t)b * SS + q0;
            float* Op = g_Opart + (size_t)part * NROW * HH + rbase * HH;
#pragma unroll
            for (int nt = 0; nt < 8; nt++) {
                float2 o0 = {o_acc[nt][0], o_acc[nt][1]};
                float2 o1 = {o_acc[nt][2], o_acc[nt][3]};
                *(float2*)&Op[rowA * HH + 8 * nt + 2 * qd]       = o0;
                *(float2*)&Op[(rowA + 8) * HH + 8 * nt + 2 * qd] = o1;
            }
            if (qd == 0) {
                float* ML = g_ML + ((size_t)part * NROW + rbase) * 2;
                *(float2*)&ML[rowA * 2]       = make_float2(m_run[0], l_run[0]);
                *(float2*)&ML[(rowA + 8) * 2] = make_float2(m_run[1], l_run[1]);
            }
        }
    }
}

// ============================================================================
// Kernel 2b: merge split-KV partials (exact, base-2 domain consistent).
// ============================================================================
__global__ __launch_bounds__(128) void combine_kernel()
{
    int rid = blockIdx.x * 2 + (threadIdx.x >> 6);
    int c = threadIdx.x & 63;
    int batch = rid / 3072;
    int r_in  = (rid % 3072) + 1024;
    size_t row = (size_t)batch * SS + r_in;
    int np = (r_in >= 2048) ? 4 : 2;

    float2 ml[4];
    float m = -1e30f;
#pragma unroll
    for (int p = 0; p < 4; p++) {
        if (p < np) {
            ml[p] = *(float2*)&g_ML[((size_t)p * NROW + row) * 2];
            m = fmaxf(m, ml[p].x);
        }
    }
    float num = 0.f, den = 0.f;
#pragma unroll
    for (int p = 0; p < 4; p++) {
        if (p < np) {
            float a = exp2f(ml[p].x - m);    // m's are log2-domain
            den += ml[p].y * a;
            num += g_Opart[(size_t)p * NROW * HH + row * HH + c] * a;
        }
    }
    g_O[row * HH + c] = num / den;
}

// ============================================================================
// Kernel 3: output projection, tf32 mma, fully vectorized fragments.
// ============================================================================
__global__ __launch_bounds__(256) void outproj_tf32_kernel(
    const float* __restrict__ bo, float* __restrict__ out)
{
    extern __shared__ float sm[];
    float* Os  = sm;              // 128 x 80
    float* Wst = sm + 128 * 80;   // 64 x 80  (Wo^T tile, k contig)

    const int row0 = blockIdx.x * 128, n0 = blockIdx.y * 64;
    const int t = threadIdx.x, w = t >> 5, lane = t & 31;
    const int qd = lane & 3, ln4 = lane >> 2;
    const int rowA = 16 * w + ln4;

#pragma unroll
    for (int l = 0; l < 8; l++) {
        int u = t + l * 256, r = u >> 4, c4 = u & 15;
        float4 v = *(const float4*)(g_O + (size_t)(row0 + r) * HH + c4 * 4);
        v.x = rne(v.x); v.y = rne(v.y); v.z = rne(v.z); v.w = rne(v.w);
        *(float4*)&Os[r * 80 + c4 * 4] = v;
    }
#pragma unroll
    for (int l = 0; l < 4; l++) {
        int u = t + l * 256, r = u >> 4, c4 = u & 15;
        *(float4*)&Wst[r * 80 + c4 * 4] =
            *(const float4*)(g_Wot + (size_t)(n0 + r) * HH + c4 * 4);
    }
    __syncthreads();

    float acc[8][4];
#pragma unroll
    for (int nt = 0; nt < 8; nt++)
#pragma unroll
        for (int v = 0; v < 4; v++) acc[nt][v] = 0.f;

#pragma unroll
    for (int jj = 0; jj < 4; jj++) {
        int ub = (qd + 4 * jj) * 4;
        float4 f0 = *(float4*)&Os[rowA * 80 + ub];
        float4 f1 = *(float4*)&Os[(rowA + 8) * 80 + ub];
        unsigned a0[4] = {FU(f0.x), FU(f1.x), FU(f0.y), FU(f1.y)};
        unsigned a1[4] = {FU(f0.z), FU(f1.z), FU(f0.w), FU(f1.w)};
#pragma unroll
        for (int nt = 0; nt < 8; nt++) {
            float4 fW = *(float4*)&Wst[(8 * nt + ln4) * 80 + ub];
            unsigned b0[2] = {FU(fW.x), FU(fW.y)};
            unsigned b1[2] = {FU(fW.z), FU(fW.w)};
            mma_tf32(acc[nt], a0, b0);
            mma_tf32(acc[nt], a1, b1);
        }
    }

#pragma unroll
    for (int nt = 0; nt < 8; nt++) {
        int c = 8 * nt + 2 * qd;
        int row = row0 + rowA;
        float b0 = bo[n0 + c], b1 = bo[n0 + c + 1];
        float2 v0 = {acc[nt][0] + b0, acc[nt][1] + b1};
        float2 v1 = {acc[nt][2] + b0, acc[nt][3] + b1};
        *(float2*)(out + (size_t)row * DD + n0 + c)       = v0;
        *(float2*)(out + (size_t)(row + 8) * DD + n0 + c) = v1;
    }
}

// ============================================================================
extern "C" void kernel_launch(void* const* d_in, const int* in_sizes, int n_in,
                              void* d_out, int out_size)
{
    const float* x  = (const float*)d_in[0];
    const float* Wq = (const float*)d_in[1];
    const float* bq = (const float*)d_in[2];
    const float* Wk = (const float*)d_in[3];
    const float* bk = (const float*)d_in[4];
    const float* Wv = (const float*)d_in[5];
    const float* bv = (const float*)d_in[6];
    const float* Wo = (const float*)d_in[7];
    const float* bo = (const float*)d_in[8];
    float* out = (float*)d_out;

    const int smem_61k = (128 * 80 + 64 * 80) * 4;   // 61440 (qkv / outproj)
    const int smem_fl  = (3 * 64 * 80) * 4;          // 61440 (flash)

    static int attr_set = 0;
    if (!attr_set) {
        cudaFuncSetAttribute(qkv_tf32_kernel,
                             cudaFuncAttributeMaxDynamicSharedMemorySize, smem_61k);
        cudaFuncSetAttribute(flash_tf32_kernel,
                             cudaFuncAttributeMaxDynamicSharedMemorySize, smem_fl);
        cudaFuncSetAttribute(outproj_tf32_kernel,
                             cudaFuncAttributeMaxDynamicSharedMemorySize, smem_61k);
        attr_set = 1;
    }

    prep_weights<<<dim3(128, 4), 256>>>(Wq, Wk, Wv, Wo);
    qkv_tf32_kernel<<<dim3(NROW / 128, 3), 256, smem_61k>>>(x, bq, bk, bv);
    flash_tf32_kernel<<<444, 128, smem_fl>>>();
    combine_kernel<<<(BB * 3072) / 2, 128>>>();
    outproj_tf32_kernel<<<dim3(NROW / 128, DD / 64), 256, smem_61k>>>(bo, out);
}